// round 1
// baseline (speedup 1.0000x reference)
#include <cuda_runtime.h>
#include <math.h>

#define TOTAL 349525
#define HID 128

// Depth tables
static const int  h_SIZES[10] = {1,4,16,64,256,1024,4096,16384,65536,262144};
static const long h_OFFS[11]  = {0,1,5,21,85,341,1365,5461,21845,87381,349525};

__constant__ int c_OFFS[11] = {0,1,5,21,85,341,1365,5461,21845,87381,349525};

// Persistent tree hidden state [TOTAL,128] and conv scratch (largest conv level: d=8)
__device__ float g_h[(size_t)TOTAL * HID];
__device__ float g_tmp[(size_t)65536 * HID];

// ---------------- Morton helpers ----------------
__device__ __forceinline__ int deint(int x) {
    x &= 0x55555555;
    x = (x | (x >> 1)) & 0x33333333;
    x = (x | (x >> 2)) & 0x0F0F0F0F;
    x = (x | (x >> 4)) & 0x00FF00FF;
    x = (x | (x >> 8)) & 0x0000FFFF;
    return x;
}
__device__ __forceinline__ int ileave(int x) {
    x &= 0xFFFF;
    x = (x | (x << 8)) & 0x00FF00FF;
    x = (x | (x << 4)) & 0x0F0F0F0F;
    x = (x | (x << 2)) & 0x33333333;
    x = (x | (x << 1)) & 0x55555555;
    return x;
}

// ============================================================================
// Kernel 1: in_proj. Tile = 64 nodes x 128 outputs, K=40 (feat + pos-encode).
// Pos-encode computed on the fly into SMEM. 128 threads, 8x8 microtile each.
// Writes g_h for ALL depths in one launch (depth derived per node).
// ============================================================================
__global__ void k_inproj(const float* __restrict__ feats,
                         const float* __restrict__ W,      // [128,40]
                         const float* __restrict__ bias)   // [128]
{
    __shared__ float As[40][65];   // [k][m]
    __shared__ float Bs[40][129];  // [k][n]
    const int m0  = blockIdx.x * 64;
    const int tid = threadIdx.x;

    // Stage W: 5120 contiguous floats, coalesced
    #pragma unroll 8
    for (int r = 0; r < 40; r++) {
        int i = tid + 128 * r;          // 0..5119
        int n = i / 40, k = i % 40;
        Bs[k][n] = W[i];
    }

    // Build A: thread t (<64) computes node m0+t's 40-dim input row
    if (tid < 64) {
        int g = m0 + tid;
        if (g < TOTAL) {
            int d = 0;
            while (d < 9 && g >= c_OFFS[d + 1]) d++;
            int i  = g - c_OFFS[d];
            int ix = deint(i), iy = deint(i >> 1);
            float inv = 1.0f / (float)(1 << d);     // exact (power of two)
            float px = ((float)ix + 0.5f) * inv;
            float py = ((float)iy + 0.5f) * inv;
            float dn = (float)d / 9.0f;
            As[0][tid] = feats[g];
            As[1][tid] = px; As[2][tid] = py; As[3][tid] = dn;
            const float TWOPI = 6.283185307179586f;
            float pos3[3] = {px, py, dn};
            #pragma unroll
            for (int p = 0; p < 3; p++) {
                float t = pos3[p] * TWOPI;
                float f = 1.0f;
                #pragma unroll
                for (int k = 0; k < 6; k++) {
                    float s, c;
                    sincosf(t * f, &s, &c);
                    As[4 + 12 * p + k][tid]     = s;
                    As[4 + 12 * p + 6 + k][tid] = c;
                    f *= 2.0f;
                }
            }
        } else {
            #pragma unroll
            for (int k = 0; k < 40; k++) As[k][tid] = 0.0f;
        }
    }
    __syncthreads();

    const int my = tid >> 4;   // 0..7 (row group)
    const int nx = tid & 15;   // 0..15 (col group)
    float acc[8][8];
    #pragma unroll
    for (int r = 0; r < 8; r++)
        #pragma unroll
        for (int s = 0; s < 8; s++) acc[r][s] = 0.0f;

    #pragma unroll
    for (int k = 0; k < 40; k++) {
        float a[8], b[8];
        #pragma unroll
        for (int r = 0; r < 8; r++) a[r] = As[k][my + 8 * r];
        #pragma unroll
        for (int s = 0; s < 8; s++) b[s] = Bs[k][nx + 16 * s];
        #pragma unroll
        for (int r = 0; r < 8; r++)
            #pragma unroll
            for (int s = 0; s < 8; s++) acc[r][s] += a[r] * b[s];
    }

    float bv[8];
    #pragma unroll
    for (int s = 0; s < 8; s++) bv[s] = bias[nx + 16 * s];
    #pragma unroll
    for (int r = 0; r < 8; r++) {
        int m = m0 + my + 8 * r;
        if (m < TOTAL) {
            #pragma unroll
            for (int s = 0; s < 8; s++)
                g_h[(size_t)m * HID + nx + 16 * s] = acc[r][s] + bv[s];
        }
    }
}

// ============================================================================
// Kernel 2: quadconv at depth d. GEMM C[M,128] = X[M,1152] @ W^T, X gathered
// from the 3x3 Morton-neighbor stencil. Tile 64x128, K chunks of 32, output
// ReLU into g_tmp.
// ============================================================================
__global__ void k_conv(long hoff, const float* __restrict__ W,   // [128,1152]
                       const float* __restrict__ bias, int M, int d)
{
    const float* hdep = g_h + hoff;
    __shared__ int   nk[64][9];
    __shared__ float As[32][65];
    __shared__ float Bs[32][129];
    const int m0  = blockIdx.x * 64;
    const int tid = threadIdx.x;
    const int res = 1 << d;

    // Neighbor key table for this tile
    for (int idx = tid; idx < 64 * 9; idx += 128) {
        int m = idx / 9, j = idx % 9;
        int node = m0 + m, key = -1;
        if (node < M) {
            int ix = deint(node), iy = deint(node >> 1);
            int nx2 = ix + (j % 3) - 1;
            int ny2 = iy + (j / 3) - 1;
            if (nx2 >= 0 && nx2 < res && ny2 >= 0 && ny2 < res)
                key = ileave(nx2) | (ileave(ny2) << 1);
        }
        nk[m][j] = key;
    }
    __syncthreads();

    const int my = tid >> 4;
    const int nx = tid & 15;
    float acc[8][8];
    #pragma unroll
    for (int r = 0; r < 8; r++)
        #pragma unroll
        for (int s = 0; s < 8; s++) acc[r][s] = 0.0f;

    for (int j = 0; j < 9; j++) {
        for (int kc = 0; kc < 4; kc++) {
            const int c0 = kc * 32;
            // A chunk: gathered rows, coalesced (whole warp reads one node's 32 chans)
            #pragma unroll
            for (int r = 0; r < 16; r++) {
                int i = tid + 128 * r;
                int m = i >> 5, k = i & 31;
                int key = nk[m][j];
                As[k][m] = (key >= 0) ? hdep[(size_t)key * HID + c0 + k] : 0.0f;
            }
            // B chunk
            const float* Wj = W + j * 128 + c0;
            #pragma unroll
            for (int r = 0; r < 32; r++) {
                int i = tid + 128 * r;
                int n = i >> 5, k = i & 31;
                Bs[k][n] = Wj[(size_t)n * 1152 + k];
            }
            __syncthreads();
            #pragma unroll
            for (int k = 0; k < 32; k++) {
                float a[8], b[8];
                #pragma unroll
                for (int r = 0; r < 8; r++) a[r] = As[k][my + 8 * r];
                #pragma unroll
                for (int s = 0; s < 8; s++) b[s] = Bs[k][nx + 16 * s];
                #pragma unroll
                for (int r = 0; r < 8; r++)
                    #pragma unroll
                    for (int s = 0; s < 8; s++) acc[r][s] += a[r] * b[s];
            }
            __syncthreads();
        }
    }

    float bv[8];
    #pragma unroll
    for (int s = 0; s < 8; s++) bv[s] = bias[nx + 16 * s];
    #pragma unroll
    for (int r = 0; r < 8; r++) {
        int m = m0 + my + 8 * r;
        if (m < M) {
            #pragma unroll
            for (int s = 0; s < 8; s++) {
                float v = acc[r][s] + bv[s];
                g_tmp[(size_t)m * HID + nx + 16 * s] = v > 0.0f ? v : 0.0f;
            }
        }
    }
}

// ============================================================================
// Kernel 3: pool (parent += mean of 4 Morton children) and optionally commit
// the conv output (g_tmp) back into g_h for the child depth.
// ============================================================================
__global__ void k_pool(long src_off, int src_is_tmp, long par_off, long com_off,
                       int do_commit, int P)
{
    long i = (long)blockIdx.x * blockDim.x + threadIdx.x;
    if (i >= (long)P * HID) return;
    int p = (int)(i >> 7), c = (int)(i & 127);
    const float* src = src_is_tmp ? g_tmp : (g_h + src_off);
    size_t base = (size_t)(4 * p) * HID + c;
    float v0 = src[base], v1 = src[base + 128], v2 = src[base + 256], v3 = src[base + 384];
    g_h[par_off + (size_t)p * HID + c] += 0.25f * (v0 + v1 + v2 + v3);
    if (do_commit) {
        float* com = g_h + com_off;
        com[base] = v0; com[base + 128] = v1; com[base + 256] = v2; com[base + 384] = v3;
    }
}

// ============================================================================
// Kernel 4: emb matmul (K=128) + fused LayerNorm + depth gain, per depth.
// LN reduction via half-warp shuffles over the 16 lanes holding a row's cols.
// ============================================================================
__global__ void k_emb(long hoff, const float* __restrict__ W,   // [128,128]
                      const float* __restrict__ eb,
                      const float* __restrict__ lg, const float* __restrict__ lb,
                      const float* __restrict__ dgain, int d, int M,
                      float* __restrict__ outp)
{
    const float* hdep = g_h + hoff;
    __shared__ float As[32][65];
    __shared__ float Bs[32][129];
    const int m0  = blockIdx.x * 64;
    const int tid = threadIdx.x;
    const int my  = tid >> 4;
    const int nx  = tid & 15;

    float acc[8][8];
    #pragma unroll
    for (int r = 0; r < 8; r++)
        #pragma unroll
        for (int s = 0; s < 8; s++) acc[r][s] = 0.0f;

    for (int kc = 0; kc < 4; kc++) {
        const int c0 = kc * 32;
        #pragma unroll
        for (int r = 0; r < 16; r++) {
            int i = tid + 128 * r;
            int m = i >> 5, k = i & 31;
            int mm = m0 + m;
            As[k][m] = (mm < M) ? hdep[(size_t)mm * HID + c0 + k] : 0.0f;
        }
        #pragma unroll
        for (int r = 0; r < 32; r++) {
            int i = tid + 128 * r;
            int n = i >> 5, k = i & 31;
            Bs[k][n] = W[(size_t)n * HID + c0 + k];
        }
        __syncthreads();
        #pragma unroll
        for (int k = 0; k < 32; k++) {
            float a[8], b[8];
            #pragma unroll
            for (int r = 0; r < 8; r++) a[r] = As[k][my + 8 * r];
            #pragma unroll
            for (int s = 0; s < 8; s++) b[s] = Bs[k][nx + 16 * s];
            #pragma unroll
            for (int r = 0; r < 8; r++)
                #pragma unroll
                for (int s = 0; s < 8; s++) acc[r][s] += a[r] * b[s];
        }
        __syncthreads();
    }

    const float gain = dgain[d];
    float bb[8], gg[8], ll[8];
    #pragma unroll
    for (int s = 0; s < 8; s++) {
        int c = nx + 16 * s;
        bb[s] = eb[c]; gg[s] = lg[c]; ll[s] = lb[c];
    }

    #pragma unroll
    for (int r = 0; r < 8; r++) {
        float v[8], s1 = 0.0f;
        #pragma unroll
        for (int s = 0; s < 8; s++) { v[s] = acc[r][s] + bb[s]; s1 += v[s]; }
        // reduce over the 16 lanes (xor bits 0..3) that share this row
        #pragma unroll
        for (int msk = 8; msk >= 1; msk >>= 1) s1 += __shfl_xor_sync(0xffffffffu, s1, msk);
        float mu = s1 * (1.0f / 128.0f);
        float s2 = 0.0f;
        #pragma unroll
        for (int s = 0; s < 8; s++) { float t = v[s] - mu; s2 += t * t; }
        #pragma unroll
        for (int msk = 8; msk >= 1; msk >>= 1) s2 += __shfl_xor_sync(0xffffffffu, s2, msk);
        float inv = rsqrtf(s2 * (1.0f / 128.0f) + 1e-5f);
        int m = m0 + my + 8 * r;
        if (m < M) {
            #pragma unroll
            for (int s = 0; s < 8; s++) {
                int c = nx + 16 * s;
                outp[(size_t)m * HID + c] = gain * ((v[s] - mu) * inv * gg[s] + ll[s]);
            }
        }
    }
}

// ============================================================================
// Launch sequence (default stream; graph-capturable: kernel launches only)
// ============================================================================
extern "C" void kernel_launch(void* const* d_in, const int* in_sizes, int n_in,
                              void* d_out, int out_size)
{
    const float* feats = (const float*)d_in[0];
    const float* inW   = (const float*)d_in[1];
    const float* inb   = (const float*)d_in[2];
    const float* convW = (const float*)d_in[3];
    const float* convb = (const float*)d_in[4];
    const float* embW  = (const float*)d_in[5];
    const float* embb  = (const float*)d_in[6];
    const float* lng   = (const float*)d_in[7];
    const float* lnb   = (const float*)d_in[8];
    const float* dg    = (const float*)d_in[9];
    float* out = (float*)d_out;

    // 1. in_proj for all nodes
    k_inproj<<<(TOTAL + 63) / 64, 128>>>(feats, inW, inb);

    // 2. pool depth 9 -> 8 (h[9] is raw in_proj; no commit)
    {
        int P = h_SIZES[8];
        long n = (long)P * HID;
        k_pool<<<(unsigned)((n + 255) / 256), 256>>>(h_OFFS[9] * HID, 0,
                                                     h_OFFS[8] * HID, 0, 0, P);
    }

    // 3. conv at depth dd, then pool dd -> dd-1 (committing conv output)
    for (int dd = 8; dd >= 1; dd--) {
        int M = h_SIZES[dd];
        k_conv<<<(M + 63) / 64, 128>>>(h_OFFS[dd] * HID,
                                       convW + (size_t)dd * 128 * 1152,
                                       convb + dd * 128, M, dd);
        int P = h_SIZES[dd - 1];
        long n = (long)P * HID;
        k_pool<<<(unsigned)((n + 255) / 256), 256>>>(0, 1,
                                                     h_OFFS[dd - 1] * HID,
                                                     h_OFFS[dd] * HID, 1, P);
    }

    // 4. emb + LayerNorm + gain per depth
    for (int d = 0; d <= 9; d++) {
        int M = h_SIZES[d];
        k_emb<<<(M + 63) / 64, 128>>>(h_OFFS[d] * HID,
                                      embW + (size_t)d * 128 * 128,
                                      embb + d * 128,
                                      lng + d * 128, lnb + d * 128,
                                      dg, d, M, out + h_OFFS[d] * HID);
    }
}

// round 2
// speedup vs baseline: 1.0443x; 1.0443x over previous
#include <cuda_runtime.h>
#include <math.h>

#define TOTAL 349525
#define HID 128

// Depth tables
static const int  h_SIZES[10] = {1,4,16,64,256,1024,4096,16384,65536,262144};
static const long h_OFFS[11]  = {0,1,5,21,85,341,1365,5461,21845,87381,349525};

__constant__ int c_OFFS[11] = {0,1,5,21,85,341,1365,5461,21845,87381,349525};

// Persistent tree hidden state [TOTAL,128] and conv scratch (largest conv level: d=8)
__device__ float g_h[(size_t)TOTAL * HID];
__device__ float g_tmp[(size_t)65536 * HID];

// ---------------- Morton helpers ----------------
__device__ __forceinline__ int deint(int x) {
    x &= 0x55555555;
    x = (x | (x >> 1)) & 0x33333333;
    x = (x | (x >> 2)) & 0x0F0F0F0F;
    x = (x | (x >> 4)) & 0x00FF00FF;
    x = (x | (x >> 8)) & 0x0000FFFF;
    return x;
}
__device__ __forceinline__ int ileave(int x) {
    x &= 0xFFFF;
    x = (x | (x << 8)) & 0x00FF00FF;
    x = (x | (x << 4)) & 0x0F0F0F0F;
    x = (x | (x << 2)) & 0x33333333;
    x = (x | (x << 1)) & 0x55555555;
    return x;
}

// ============================================================================
// Kernel 1: in_proj. Tile = 64 nodes x 128 outputs, K=40 (feat + pos-encode).
// Pos-encode computed on the fly into SMEM. 128 threads, 8x8 microtile each.
// Writes g_h for ALL depths in one launch (depth derived per node).
// ============================================================================
__global__ void k_inproj(const float* __restrict__ feats,
                         const float* __restrict__ W,      // [128,40]
                         const float* __restrict__ bias)   // [128]
{
    __shared__ float As[40][65];   // [k][m]
    __shared__ float Bs[40][129];  // [k][n]
    const int m0  = blockIdx.x * 64;
    const int tid = threadIdx.x;

    // Stage W: 5120 contiguous floats, coalesced
    #pragma unroll 8
    for (int r = 0; r < 40; r++) {
        int i = tid + 128 * r;          // 0..5119
        int n = i / 40, k = i % 40;
        Bs[k][n] = W[i];
    }

    // Build A: thread t (<64) computes node m0+t's 40-dim input row
    if (tid < 64) {
        int g = m0 + tid;
        if (g < TOTAL) {
            int d = 0;
            while (d < 9 && g >= c_OFFS[d + 1]) d++;
            int i  = g - c_OFFS[d];
            int ix = deint(i), iy = deint(i >> 1);
            float inv = 1.0f / (float)(1 << d);     // exact (power of two)
            float px = ((float)ix + 0.5f) * inv;
            float py = ((float)iy + 0.5f) * inv;
            float dn = (float)d / 9.0f;
            As[0][tid] = feats[g];
            As[1][tid] = px; As[2][tid] = py; As[3][tid] = dn;
            const float TWOPI = 6.283185307179586f;
            float pos3[3] = {px, py, dn};
            #pragma unroll
            for (int p = 0; p < 3; p++) {
                float t = pos3[p] * TWOPI;
                float f = 1.0f;
                #pragma unroll
                for (int k = 0; k < 6; k++) {
                    float s, c;
                    sincosf(t * f, &s, &c);
                    As[4 + 12 * p + k][tid]     = s;
                    As[4 + 12 * p + 6 + k][tid] = c;
                    f *= 2.0f;
                }
            }
        } else {
            #pragma unroll
            for (int k = 0; k < 40; k++) As[k][tid] = 0.0f;
        }
    }
    __syncthreads();

    const int my = tid >> 4;   // 0..7 (row group)
    const int nx = tid & 15;   // 0..15 (col group)
    float acc[8][8];
    #pragma unroll
    for (int r = 0; r < 8; r++)
        #pragma unroll
        for (int s = 0; s < 8; s++) acc[r][s] = 0.0f;

    #pragma unroll
    for (int k = 0; k < 40; k++) {
        float a[8], b[8];
        #pragma unroll
        for (int r = 0; r < 8; r++) a[r] = As[k][my + 8 * r];
        #pragma unroll
        for (int s = 0; s < 8; s++) b[s] = Bs[k][nx + 16 * s];
        #pragma unroll
        for (int r = 0; r < 8; r++)
            #pragma unroll
            for (int s = 0; s < 8; s++) acc[r][s] += a[r] * b[s];
    }

    float bv[8];
    #pragma unroll
    for (int s = 0; s < 8; s++) bv[s] = bias[nx + 16 * s];
    #pragma unroll
    for (int r = 0; r < 8; r++) {
        int m = m0 + my + 8 * r;
        if (m < TOTAL) {
            #pragma unroll
            for (int s = 0; s < 8; s++)
                g_h[(size_t)m * HID + nx + 16 * s] = acc[r][s] + bv[s];
        }
    }
}

// ============================================================================
// Kernel 2: quadconv at depth d. GEMM C[M,128] = X[M,1152] @ W^T, X gathered
// from the 3x3 Morton-neighbor stencil. Tile 64x128, K chunks of 32, output
// ReLU into g_tmp.
// ============================================================================
__global__ void k_conv(long hoff, const float* __restrict__ W,   // [128,1152]
                       const float* __restrict__ bias, int M, int d)
{
    const float* hdep = g_h + hoff;
    __shared__ int   nk[64][9];
    __shared__ float As[32][65];
    __shared__ float Bs[32][129];
    const int m0  = blockIdx.x * 64;
    const int tid = threadIdx.x;
    const int res = 1 << d;

    // Neighbor key table for this tile
    for (int idx = tid; idx < 64 * 9; idx += 128) {
        int m = idx / 9, j = idx % 9;
        int node = m0 + m, key = -1;
        if (node < M) {
            int ix = deint(node), iy = deint(node >> 1);
            int nx2 = ix + (j % 3) - 1;
            int ny2 = iy + (j / 3) - 1;
            if (nx2 >= 0 && nx2 < res && ny2 >= 0 && ny2 < res)
                key = ileave(nx2) | (ileave(ny2) << 1);
        }
        nk[m][j] = key;
    }
    __syncthreads();

    const int my = tid >> 4;
    const int nx = tid & 15;
    float acc[8][8];
    #pragma unroll
    for (int r = 0; r < 8; r++)
        #pragma unroll
        for (int s = 0; s < 8; s++) acc[r][s] = 0.0f;

    for (int j = 0; j < 9; j++) {
        for (int kc = 0; kc < 4; kc++) {
            const int c0 = kc * 32;
            // A chunk: gathered rows, coalesced (whole warp reads one node's 32 chans)
            #pragma unroll
            for (int r = 0; r < 16; r++) {
                int i = tid + 128 * r;
                int m = i >> 5, k = i & 31;
                int key = nk[m][j];
                As[k][m] = (key >= 0) ? hdep[(size_t)key * HID + c0 + k] : 0.0f;
            }
            // B chunk
            const float* Wj = W + j * 128 + c0;
            #pragma unroll
            for (int r = 0; r < 32; r++) {
                int i = tid + 128 * r;
                int n = i >> 5, k = i & 31;
                Bs[k][n] = Wj[(size_t)n * 1152 + k];
            }
            __syncthreads();
            #pragma unroll
            for (int k = 0; k < 32; k++) {
                float a[8], b[8];
                #pragma unroll
                for (int r = 0; r < 8; r++) a[r] = As[k][my + 8 * r];
                #pragma unroll
                for (int s = 0; s < 8; s++) b[s] = Bs[k][nx + 16 * s];
                #pragma unroll
                for (int r = 0; r < 8; r++)
                    #pragma unroll
                    for (int s = 0; s < 8; s++) acc[r][s] += a[r] * b[s];
            }
            __syncthreads();
        }
    }

    float bv[8];
    #pragma unroll
    for (int s = 0; s < 8; s++) bv[s] = bias[nx + 16 * s];
    #pragma unroll
    for (int r = 0; r < 8; r++) {
        int m = m0 + my + 8 * r;
        if (m < M) {
            #pragma unroll
            for (int s = 0; s < 8; s++) {
                float v = acc[r][s] + bv[s];
                g_tmp[(size_t)m * HID + nx + 16 * s] = v > 0.0f ? v : 0.0f;
            }
        }
    }
}

// ============================================================================
// Kernel 3: pool (parent += mean of 4 Morton children) and optionally commit
// the conv output (g_tmp) back into g_h for the child depth.
// ============================================================================
__global__ void k_pool(long src_off, int src_is_tmp, long par_off, long com_off,
                       int do_commit, int P)
{
    long i = (long)blockIdx.x * blockDim.x + threadIdx.x;
    if (i >= (long)P * HID) return;
    int p = (int)(i >> 7), c = (int)(i & 127);
    const float* src = src_is_tmp ? g_tmp : (g_h + src_off);
    size_t base = (size_t)(4 * p) * HID + c;
    float v0 = src[base], v1 = src[base + 128], v2 = src[base + 256], v3 = src[base + 384];
    g_h[par_off + (size_t)p * HID + c] += 0.25f * (v0 + v1 + v2 + v3);
    if (do_commit) {
        float* com = g_h + com_off;
        com[base] = v0; com[base + 128] = v1; com[base + 256] = v2; com[base + 384] = v3;
    }
}

// ============================================================================
// Kernel 4: emb matmul (K=128) + fused LayerNorm + depth gain, per depth.
// LN reduction via half-warp shuffles over the 16 lanes holding a row's cols.
// ============================================================================
__global__ void k_emb(long hoff, const float* __restrict__ W,   // [128,128]
                      const float* __restrict__ eb,
                      const float* __restrict__ lg, const float* __restrict__ lb,
                      const float* __restrict__ dgain, int d, int M,
                      float* __restrict__ outp)
{
    const float* hdep = g_h + hoff;
    __shared__ float As[32][65];
    __shared__ float Bs[32][129];
    const int m0  = blockIdx.x * 64;
    const int tid = threadIdx.x;
    const int my  = tid >> 4;
    const int nx  = tid & 15;

    float acc[8][8];
    #pragma unroll
    for (int r = 0; r < 8; r++)
        #pragma unroll
        for (int s = 0; s < 8; s++) acc[r][s] = 0.0f;

    for (int kc = 0; kc < 4; kc++) {
        const int c0 = kc * 32;
        #pragma unroll
        for (int r = 0; r < 16; r++) {
            int i = tid + 128 * r;
            int m = i >> 5, k = i & 31;
            int mm = m0 + m;
            As[k][m] = (mm < M) ? hdep[(size_t)mm * HID + c0 + k] : 0.0f;
        }
        #pragma unroll
        for (int r = 0; r < 32; r++) {
            int i = tid + 128 * r;
            int n = i >> 5, k = i & 31;
            Bs[k][n] = W[(size_t)n * HID + c0 + k];
        }
        __syncthreads();
        #pragma unroll
        for (int k = 0; k < 32; k++) {
            float a[8], b[8];
            #pragma unroll
            for (int r = 0; r < 8; r++) a[r] = As[k][my + 8 * r];
            #pragma unroll
            for (int s = 0; s < 8; s++) b[s] = Bs[k][nx + 16 * s];
            #pragma unroll
            for (int r = 0; r < 8; r++)
                #pragma unroll
                for (int s = 0; s < 8; s++) acc[r][s] += a[r] * b[s];
        }
        __syncthreads();
    }

    const float gain = dgain[d];
    float bb[8], gg[8], ll[8];
    #pragma unroll
    for (int s = 0; s < 8; s++) {
        int c = nx + 16 * s;
        bb[s] = eb[c]; gg[s] = lg[c]; ll[s] = lb[c];
    }

    #pragma unroll
    for (int r = 0; r < 8; r++) {
        float v[8], s1 = 0.0f;
        #pragma unroll
        for (int s = 0; s < 8; s++) { v[s] = acc[r][s] + bb[s]; s1 += v[s]; }
        // reduce over the 16 lanes (xor bits 0..3) that share this row
        #pragma unroll
        for (int msk = 8; msk >= 1; msk >>= 1) s1 += __shfl_xor_sync(0xffffffffu, s1, msk);
        float mu = s1 * (1.0f / 128.0f);
        float s2 = 0.0f;
        #pragma unroll
        for (int s = 0; s < 8; s++) { float t = v[s] - mu; s2 += t * t; }
        #pragma unroll
        for (int msk = 8; msk >= 1; msk >>= 1) s2 += __shfl_xor_sync(0xffffffffu, s2, msk);
        float inv = rsqrtf(s2 * (1.0f / 128.0f) + 1e-5f);
        int m = m0 + my + 8 * r;
        if (m < M) {
            #pragma unroll
            for (int s = 0; s < 8; s++) {
                int c = nx + 16 * s;
                outp[(size_t)m * HID + c] = gain * ((v[s] - mu) * inv * gg[s] + ll[s]);
            }
        }
    }
}

// ============================================================================
// Launch sequence (default stream; graph-capturable: kernel launches only)
// ============================================================================
extern "C" void kernel_launch(void* const* d_in, const int* in_sizes, int n_in,
                              void* d_out, int out_size)
{
    const float* feats = (const float*)d_in[0];
    const float* inW   = (const float*)d_in[1];
    const float* inb   = (const float*)d_in[2];
    const float* convW = (const float*)d_in[3];
    const float* convb = (const float*)d_in[4];
    const float* embW  = (const float*)d_in[5];
    const float* embb  = (const float*)d_in[6];
    const float* lng   = (const float*)d_in[7];
    const float* lnb   = (const float*)d_in[8];
    const float* dg    = (const float*)d_in[9];
    float* out = (float*)d_out;

    // 1. in_proj for all nodes
    k_inproj<<<(TOTAL + 63) / 64, 128>>>(feats, inW, inb);

    // 2. pool depth 9 -> 8 (h[9] is raw in_proj; no commit)
    {
        int P = h_SIZES[8];
        long n = (long)P * HID;
        k_pool<<<(unsigned)((n + 255) / 256), 256>>>(h_OFFS[9] * HID, 0,
                                                     h_OFFS[8] * HID, 0, 0, P);
    }

    // 3. conv at depth dd, then pool dd -> dd-1 (committing conv output)
    for (int dd = 8; dd >= 1; dd--) {
        int M = h_SIZES[dd];
        k_conv<<<(M + 63) / 64, 128>>>(h_OFFS[dd] * HID,
                                       convW + (size_t)dd * 128 * 1152,
                                       convb + dd * 128, M, dd);
        int P = h_SIZES[dd - 1];
        long n = (long)P * HID;
        k_pool<<<(unsigned)((n + 255) / 256), 256>>>(0, 1,
                                                     h_OFFS[dd - 1] * HID,
                                                     h_OFFS[dd] * HID, 1, P);
    }

    // 4. emb + LayerNorm + gain per depth
    for (int d = 0; d <= 9; d++) {
        int M = h_SIZES[d];
        k_emb<<<(M + 63) / 64, 128>>>(h_OFFS[d] * HID,
                                      embW + (size_t)d * 128 * 128,
                                      embb + d * 128,
                                      lng + d * 128, lnb + d * 128,
                                      dg, d, M, out + h_OFFS[d] * HID);
    }
}